// round 16
// baseline (speedup 1.0000x reference)
#include <cuda_runtime.h>
#include <stdint.h>

// Problem constants (fixed shapes per reference)
#define VOCAB   20000
#define TOPK    8
#define GLOVE   300
#define ROW_F   (TOPK * 2 * GLOVE)   // 4800 floats per vocab row
#define OUTC    100
#define B       32
#define L       128
#define NLAB    8
#define NPOS    (B * L)              // 4096
#define NLABTOT (NPOS * NLAB)        // 32768

#define KSPLIT  15
#define KCH     20                   // k0 = kc*20, 20 % 4 == 0 -> float4-aligned
#define KQ      (KCH / 4)            // 5
#define PTILE   32
#define NPT     (NPOS / PTILE)       // 128
#define GT6     200
#define AP      36
#define WP      104

// Device scratch (no allocations allowed). Device globals start zeroed at
// module load; k_final re-clears all flags AFTER k_rowsum has consumed them
// (stream-ordered, no intra-kernel race), so the all-zero invariant holds
// across graph replays: mark -> rowsum -> gemm -> final(clear).
__device__ unsigned int g_flags[VOCAB];
__device__ float g_lsum[VOCAB * GLOVE];            // 24 MB
__device__ float g_part[KSPLIT * NPOS * OUTC];     // 24.6 MB: split-K partials

// ---------------------------------------------------------------------------
// Kernel 1: mark used vocab entries
// ---------------------------------------------------------------------------
__global__ void k_mark_flags(const int* __restrict__ labels) {
    int i = blockIdx.x * blockDim.x + threadIdx.x;
    if (i < NLABTOT) g_flags[labels[i]] = 1u;
}

// ---------------------------------------------------------------------------
// Kernel 2: per-vocab row reduction (DRAM floor: measured 53.3 us, 77% DRAM).
// Read-only on g_flags (clearing happens later in k_final -> no race).
// ---------------------------------------------------------------------------
__global__ __launch_bounds__(256) void k_rowsum(const float* __restrict__ table) {
    const int v = blockIdx.x;
    if (!g_flags[v]) return;
    const float* __restrict__ row = table + (size_t)v * ROW_F;
    const int t = threadIdx.x;
    const float scale = 1.0f / 128.0f;

    {
        float s = 0.0f;
        #pragma unroll
        for (int r = 0; r < 16; ++r) s += row[r * GLOVE + t];
        g_lsum[v * GLOVE + t] = s * scale;
    }
    if (t < GLOVE - 256) {
        const int d = t + 256;
        float s = 0.0f;
        #pragma unroll
        for (int r = 0; r < 16; ++r) s += row[r * GLOVE + d];
        g_lsum[v * GLOVE + d] = s * scale;
    }
}

// ---------------------------------------------------------------------------
// Kernel 3 (v6, proven R13): split-K GEMM, fused warp-coalesced float4 gather.
// KSPLIT=15, KCH=20 -> grid 1920 = 128 pos-tiles x 15 K-chunks, ~10 blk/SM.
// Labels direct from gmem (L2-resident, lane-broadcast); single sync.
// Mainloop: thread tile 4 pos x 4 outs; per k one float4 A + one float4 W.
// ---------------------------------------------------------------------------
__global__ __launch_bounds__(GT6) void k_gemm6(
    const int* __restrict__ labels,
    const float* __restrict__ w)          // [100, 300]
{
    __shared__ float A_t[KCH][AP];        // [k][pos]
    __shared__ float W_t[KCH][WP];        // [k][out]

    const int tid   = threadIdx.x;
    const int kc    = blockIdx.x % KSPLIT;
    const int pt    = blockIdx.x / KSPLIT;
    const int pbase = pt * PTILE;
    const int k0    = kc * KCH;

    // ---- stage W chunk transposed, float4 over k (500 quads, 2.5/thread) ----
    for (int j = tid; j < OUTC * KQ; j += GT6) {
        const int o   = j / KQ;
        const int kkq = j - o * KQ;
        const int kk  = kkq * 4;
        const float4 v = *reinterpret_cast<const float4*>(
            &w[o * GLOVE + k0 + kk]);
        W_t[kk + 0][o] = v.x;
        W_t[kk + 1][o] = v.y;
        W_t[kk + 2][o] = v.z;
        W_t[kk + 3][o] = v.w;
    }

    // ---- fused float4 gather, pos-major; labels direct from gmem ----
    if (tid < PTILE * KQ) {
        const int pp  = tid / KQ;         // 0..31
        const int kkq = tid - pp * KQ;    // 0..4
        const int kg  = k0 + kkq * 4;
        const int* __restrict__ lab = labels + (pbase + pp) * NLAB;
        float4 s = make_float4(0.f, 0.f, 0.f, 0.f);
        #pragma unroll
        for (int m = 0; m < NLAB; ++m) {
            const float4 v = *reinterpret_cast<const float4*>(
                &g_lsum[lab[m] * GLOVE + kg]);
            s.x += v.x; s.y += v.y; s.z += v.z; s.w += v.w;
        }
        const int kk = kkq * 4;
        A_t[kk + 0][pp] = s.x;
        A_t[kk + 1][pp] = s.y;
        A_t[kk + 2][pp] = s.z;
        A_t[kk + 3][pp] = s.w;
    }
    __syncthreads();

    const int pg = tid / 25;   // 0..7 -> pos quad
    const int og = tid % 25;   // 0..24 -> out quad

    float acc[4][4];
    #pragma unroll
    for (int i = 0; i < 4; ++i)
        #pragma unroll
        for (int j = 0; j < 4; ++j) acc[i][j] = 0.0f;

    #pragma unroll
    for (int kk = 0; kk < KCH; ++kk) {
        const float4 a  = *reinterpret_cast<const float4*>(&A_t[kk][pg * 4]);
        const float4 wv = *reinterpret_cast<const float4*>(&W_t[kk][og * 4]);
        const float av[4] = {a.x, a.y, a.z, a.w};
        const float wa[4] = {wv.x, wv.y, wv.z, wv.w};
        #pragma unroll
        for (int i = 0; i < 4; ++i)
            #pragma unroll
            for (int j = 0; j < 4; ++j)
                acc[i][j] = fmaf(av[i], wa[j], acc[i][j]);
    }

    // write partials: g_part[kc][pos][out], float4 per pos
    float* dst = g_part + (size_t)kc * (NPOS * OUTC);
    #pragma unroll
    for (int i = 0; i < 4; ++i) {
        const int p = pbase + pg * 4 + i;
        float4 r = make_float4(acc[i][0], acc[i][1], acc[i][2], acc[i][3]);
        *reinterpret_cast<float4*>(&dst[p * OUTC + og * 4]) = r;
    }
}

// ---------------------------------------------------------------------------
// Kernel 4: final reduction, ONE THREAD PER ELEMENT (409600 threads, MLP=15,
// coalesced over o within warps). Also clears g_flags for the next replay
// (safe: runs after k_rowsum in stream order).
// ---------------------------------------------------------------------------
#define FIN_THREADS 256
#define FIN_TOTAL   (NPOS * OUTC)      // 409600

__global__ __launch_bounds__(FIN_THREADS) void k_final(
    const float* __restrict__ bias,
    float* __restrict__ out)
{
    const int i = blockIdx.x * FIN_THREADS + threadIdx.x;
    if (i < VOCAB) g_flags[i] = 0u;    // restore invariant for next replay
    if (i >= FIN_TOTAL) return;
    const int o = i % OUTC;

    float s = bias[o];
    #pragma unroll
    for (int kc = 0; kc < KSPLIT; ++kc)
        s += g_part[(size_t)kc * (NPOS * OUTC) + i];
    out[i] = s;
}

// ---------------------------------------------------------------------------
extern "C" void kernel_launch(void* const* d_in, const int* in_sizes, int n_in,
                              void* d_out, int out_size) {
    const int*   labels = (const int*)  d_in[0];   // [32, 128, 8] int32
    const float* table  = (const float*)d_in[1];   // [20000, 8, 600] f32
    const float* conv_w = (const float*)d_in[2];   // [100, 300]
    const float* conv_b = (const float*)d_in[3];   // [100]
    float*       out    = (float*)d_out;           // [32, 128, 100]

    (void)in_sizes; (void)n_in; (void)out_size;

    k_mark_flags<<<(NLABTOT + 255) / 256, 256>>>(labels);
    k_rowsum<<<VOCAB, 256>>>(table);
    k_gemm6<<<NPT * KSPLIT, GT6>>>(labels, conv_w);
    k_final<<<(FIN_TOTAL + FIN_THREADS - 1) / FIN_THREADS, FIN_THREADS>>>(conv_b, out);
}

// round 17
// speedup vs baseline: 1.1698x; 1.1698x over previous
#include <cuda_runtime.h>
#include <stdint.h>

// Problem constants (fixed shapes per reference)
#define VOCAB   20000
#define TOPK    8
#define GLOVE   300
#define ROW_F   (TOPK * 2 * GLOVE)   // 4800 floats per vocab row
#define OUTC    100
#define B       32
#define L       128
#define NLAB    8
#define NPOS    (B * L)              // 4096
#define NLABTOT (NPOS * NLAB)        // 32768

#define KSPLIT  15
#define KCH     20                   // k0 = kc*20, 20 % 4 == 0 -> float4-aligned
#define KQ      (KCH / 4)            // 5
#define PTILE   32
#define NPT     (NPOS / PTILE)       // 128
#define GT6     200
#define AP      36
#define WP      104

// Device scratch (no allocations allowed). Device globals start zeroed at
// module load; k_final re-clears all flags AFTER k_rowsum consumed them
// (stream-ordered -> race-free), restoring the all-zero invariant for the
// next graph replay: mark -> rowsum -> gemm -> final(clear).
__device__ unsigned int g_flags[VOCAB];
__device__ float g_lsum[VOCAB * GLOVE];            // 24 MB
__device__ float g_part[KSPLIT * NPOS * OUTC];     // 24.6 MB: split-K partials

// ---------------------------------------------------------------------------
// Kernel 1: mark used vocab entries
// ---------------------------------------------------------------------------
__global__ void k_mark_flags(const int* __restrict__ labels) {
    int i = blockIdx.x * blockDim.x + threadIdx.x;
    if (i < NLABTOT) g_flags[labels[i]] = 1u;
}

// ---------------------------------------------------------------------------
// Kernel 2: per-vocab row reduction (measured 53.3 us, 77% DRAM = floor).
// Read-only on g_flags (clearing deferred to k_final -> no race).
// ---------------------------------------------------------------------------
__global__ __launch_bounds__(256) void k_rowsum(const float* __restrict__ table) {
    const int v = blockIdx.x;
    if (!g_flags[v]) return;
    const float* __restrict__ row = table + (size_t)v * ROW_F;
    const int t = threadIdx.x;
    const float scale = 1.0f / 128.0f;

    {
        float s = 0.0f;
        #pragma unroll
        for (int r = 0; r < 16; ++r) s += row[r * GLOVE + t];
        g_lsum[v * GLOVE + t] = s * scale;
    }
    if (t < GLOVE - 256) {
        const int d = t + 256;
        float s = 0.0f;
        #pragma unroll
        for (int r = 0; r < 16; ++r) s += row[r * GLOVE + d];
        g_lsum[v * GLOVE + d] = s * scale;
    }
}

// ---------------------------------------------------------------------------
// Kernel 3 (v6, proven R13, measured 21.2 us): split-K GEMM with fused,
// warp-coalesced float4 gather. KSPLIT=15, KCH=20 -> grid 1920, ~10 blk/SM.
// Labels direct from gmem (L2-resident, lane-broadcast); single sync.
// Mainloop: thread tile 4 pos x 4 outs; per k one float4 A + one float4 W.
// ---------------------------------------------------------------------------
__global__ __launch_bounds__(GT6) void k_gemm6(
    const int* __restrict__ labels,
    const float* __restrict__ w)          // [100, 300]
{
    __shared__ float A_t[KCH][AP];        // [k][pos]
    __shared__ float W_t[KCH][WP];        // [k][out]

    const int tid   = threadIdx.x;
    const int kc    = blockIdx.x % KSPLIT;
    const int pt    = blockIdx.x / KSPLIT;
    const int pbase = pt * PTILE;
    const int k0    = kc * KCH;

    // ---- stage W chunk transposed, float4 over k (500 quads, 2.5/thread) ----
    for (int j = tid; j < OUTC * KQ; j += GT6) {
        const int o   = j / KQ;
        const int kkq = j - o * KQ;
        const int kk  = kkq * 4;
        const float4 v = *reinterpret_cast<const float4*>(
            &w[o * GLOVE + k0 + kk]);
        W_t[kk + 0][o] = v.x;
        W_t[kk + 1][o] = v.y;
        W_t[kk + 2][o] = v.z;
        W_t[kk + 3][o] = v.w;
    }

    // ---- fused float4 gather, pos-major; labels direct from gmem ----
    if (tid < PTILE * KQ) {
        const int pp  = tid / KQ;         // 0..31
        const int kkq = tid - pp * KQ;    // 0..4
        const int kg  = k0 + kkq * 4;
        const int* __restrict__ lab = labels + (pbase + pp) * NLAB;
        float4 s = make_float4(0.f, 0.f, 0.f, 0.f);
        #pragma unroll
        for (int m = 0; m < NLAB; ++m) {
            const float4 v = *reinterpret_cast<const float4*>(
                &g_lsum[lab[m] * GLOVE + kg]);
            s.x += v.x; s.y += v.y; s.z += v.z; s.w += v.w;
        }
        const int kk = kkq * 4;
        A_t[kk + 0][pp] = s.x;
        A_t[kk + 1][pp] = s.y;
        A_t[kk + 2][pp] = s.z;
        A_t[kk + 3][pp] = s.w;
    }
    __syncthreads();

    const int pg = tid / 25;   // 0..7 -> pos quad
    const int og = tid % 25;   // 0..24 -> out quad

    float acc[4][4];
    #pragma unroll
    for (int i = 0; i < 4; ++i)
        #pragma unroll
        for (int j = 0; j < 4; ++j) acc[i][j] = 0.0f;

    #pragma unroll
    for (int kk = 0; kk < KCH; ++kk) {
        const float4 a  = *reinterpret_cast<const float4*>(&A_t[kk][pg * 4]);
        const float4 wv = *reinterpret_cast<const float4*>(&W_t[kk][og * 4]);
        const float av[4] = {a.x, a.y, a.z, a.w};
        const float wa[4] = {wv.x, wv.y, wv.z, wv.w};
        #pragma unroll
        for (int i = 0; i < 4; ++i)
            #pragma unroll
            for (int j = 0; j < 4; ++j)
                acc[i][j] = fmaf(av[i], wa[j], acc[i][j]);
    }

    // write partials: g_part[kc][pos][out], float4 per pos
    float* dst = g_part + (size_t)kc * (NPOS * OUTC);
    #pragma unroll
    for (int i = 0; i < 4; ++i) {
        const int p = pbase + pg * 4 + i;
        float4 r = make_float4(acc[i][0], acc[i][1], acc[i][2], acc[i][3]);
        *reinterpret_cast<float4*>(&dst[p * OUTC + og * 4]) = r;
    }
}

// ---------------------------------------------------------------------------
// Kernel 4 (R13 float4 form): final reduction of split-K partials + bias.
// One thread per output QUAD: 102400 threads, 15x LDG.128 each (MLP=15).
// Also clears g_flags for the next replay (runs after rowsum: race-free).
// ---------------------------------------------------------------------------
#define FIN_THREADS 256
#define FIN_TOTAL   (NPOS * 25)        // 102400 quads

__global__ __launch_bounds__(FIN_THREADS) void k_final(
    const float* __restrict__ bias,
    float* __restrict__ out)
{
    const int i = blockIdx.x * FIN_THREADS + threadIdx.x;
    if (i < VOCAB) g_flags[i] = 0u;    // restore invariant for next replay
    if (i >= FIN_TOTAL) return;
    const int p = i / 25;
    const int q = (i % 25) * 4;

    float4 s = *reinterpret_cast<const float4*>(&bias[q]);
    #pragma unroll
    for (int kc = 0; kc < KSPLIT; ++kc) {
        const float4 v = *reinterpret_cast<const float4*>(
            &g_part[(size_t)kc * (NPOS * OUTC) + p * OUTC + q]);
        s.x += v.x; s.y += v.y; s.z += v.z; s.w += v.w;
    }
    *reinterpret_cast<float4*>(&out[p * OUTC + q]) = s;
}

// ---------------------------------------------------------------------------
extern "C" void kernel_launch(void* const* d_in, const int* in_sizes, int n_in,
                              void* d_out, int out_size) {
    const int*   labels = (const int*)  d_in[0];   // [32, 128, 8] int32
    const float* table  = (const float*)d_in[1];   // [20000, 8, 600] f32
    const float* conv_w = (const float*)d_in[2];   // [100, 300]
    const float* conv_b = (const float*)d_in[3];   // [100]
    float*       out    = (float*)d_out;           // [32, 128, 100]

    (void)in_sizes; (void)n_in; (void)out_size;

    k_mark_flags<<<(NLABTOT + 255) / 256, 256>>>(labels);
    k_rowsum<<<VOCAB, 256>>>(table);
    k_gemm6<<<NPT * KSPLIT, GT6>>>(labels, conv_w);
    k_final<<<(FIN_TOTAL + FIN_THREADS - 1) / FIN_THREADS, FIN_THREADS>>>(conv_b, out);
}